// round 4
// baseline (speedup 1.0000x reference)
#include <cuda_runtime.h>
#include <cuda_fp16.h>
#include <math.h>

// Problem constants (ManifoldGPRFilter: N=100000, D=64, E=1000000, L=10)
#define NMAX 100000
#define EMAX 1000000
#define DIM  64
#define LMAX 10
#define EPSV 1e-8f

// ---------------- static device scratch (no runtime allocation) ----------------
__device__ __half2 g_Xh[(size_t)NMAX * (DIM / 2)];
__device__ __half2 g_Hl[LMAX][(size_t)NMAX * (DIM / 2)];   // all 10 levels kept
__device__ int   g_deg[NMAX];
__device__ int   g_off[NMAX + 1];
__device__ int   g_cur[NMAX];
__device__ int2  g_edge[EMAX];     // packed (src, float-bits of val)

// decoupled-lookback scan state (reset every replay by k_prep)
#define SCAN_B 1024
#define MAXBLK 128
__device__ int g_agg[MAXBLK];
__device__ volatile int g_flag[MAXBLK];

// ---------------- prep: zero deg + scan flags, convert X -> fp16 ----------------
__global__ void k_prep(const float* __restrict__ X, __half2* __restrict__ Xh, int n, int n4) {
    int i = blockIdx.x * blockDim.x + threadIdx.x;
    if (i < n4) {
        float4 x = ((const float4*)X)[i];
        Xh[i * 2]     = __floats2half2_rn(x.x, x.y);
        Xh[i * 2 + 1] = __floats2half2_rn(x.z, x.w);
    }
    if (i < n) g_deg[i] = 0;
    if (i < MAXBLK) { g_agg[i] = 0; g_flag[i] = 0; }
}

__global__ void k_hist(const int* __restrict__ dst, int e) {
    int i = blockIdx.x * blockDim.x + threadIdx.x;
    if (i < e) atomicAdd(&g_deg[dst[i]], 1);
}

// ---------------- single-kernel exclusive scan (decoupled lookback) ----------------
// nb <= 98 blocks, all co-resident on 148 SMs -> sequential spin is deadlock-free.
__global__ void k_scan(int n, int nb) {
    __shared__ int sh[SCAN_B];
    __shared__ int s_prefix;
    int bid = blockIdx.x;
    int i = bid * SCAN_B + threadIdx.x;
    int v = (i < n) ? g_deg[i] : 0;
    sh[threadIdx.x] = v;
    __syncthreads();
    for (int o = 1; o < SCAN_B; o <<= 1) {
        int t = 0;
        if (threadIdx.x >= o) t = sh[threadIdx.x - o];
        __syncthreads();
        if (threadIdx.x >= o) sh[threadIdx.x] += t;
        __syncthreads();
    }
    // publish block aggregate
    if (threadIdx.x == SCAN_B - 1) {
        g_agg[bid] = sh[SCAN_B - 1];
        __threadfence();
        g_flag[bid] = 1;
    }
    // look back: sum aggregates of all preceding blocks
    if (threadIdx.x == 0) {
        int sum = 0;
        for (int b = 0; b < bid; b++) {
            while (g_flag[b] == 0) { }
            sum += g_agg[b];
        }
        s_prefix = sum;
    }
    __syncthreads();
    int pre = s_prefix;
    if (i < n) {
        int excl = pre + sh[threadIdx.x] - v;
        g_off[i] = excl;
        g_cur[i] = excl;
    }
    if (bid == nb - 1 && threadIdx.x == SCAN_B - 1)
        g_off[n] = pre + sh[SCAN_B - 1];
}

__global__ void k_scatter(const int* __restrict__ src, const int* __restrict__ dst,
                          const float* __restrict__ val, int e) {
    int i = blockIdx.x * blockDim.x + threadIdx.x;
    if (i < e) {
        int d = dst[i];
        int pos = atomicAdd(&g_cur[d], 1);
        g_edge[pos] = make_int2(src[i], __float_as_int(val[i]));
    }
}

// ---------------- fused SpMM + hyperbolic renorm (no Z traffic) ----------------
// One warp per destination row, edges in PAIRS:
//   lanes 0-15 gather edge e's 128B row; lanes 16-31 edge e+1's row.
__global__ __launch_bounds__(256)
void k_spmm_renorm(const __half2* __restrict__ Hin, __half2* __restrict__ Hout, int n) {
    int warp = (blockIdx.x * blockDim.x + threadIdx.x) >> 5;
    int lane = threadIdx.x & 31;
    if (warp >= n) return;

    int half = lane >> 4;
    int sub  = lane & 15;

    int beg = g_off[warp];
    int end = g_off[warp + 1];

    const uint2* Hrows = reinterpret_cast<const uint2*>(Hin);
    float4 acc = make_float4(0.f, 0.f, 0.f, 0.f);

    int e = beg;
    for (; e + 4 <= end; e += 4) {
        int2 ed0 = __ldg(&g_edge[e + half]);
        int2 ed1 = __ldg(&g_edge[e + 2 + half]);
        uint2 h0 = __ldg(Hrows + (size_t)ed0.x * 16 + sub);
        uint2 h1 = __ldg(Hrows + (size_t)ed1.x * 16 + sub);
        float v0 = __int_as_float(ed0.y);
        float v1 = __int_as_float(ed1.y);
        float2 a01 = __half22float2(*(const __half2*)&h0.x);
        float2 a23 = __half22float2(*(const __half2*)&h0.y);
        float2 b01 = __half22float2(*(const __half2*)&h1.x);
        float2 b23 = __half22float2(*(const __half2*)&h1.y);
        acc.x += v0 * a01.x + v1 * b01.x;
        acc.y += v0 * a01.y + v1 * b01.y;
        acc.z += v0 * a23.x + v1 * b23.x;
        acc.w += v0 * a23.y + v1 * b23.y;
    }
    if (e + 2 <= end) {
        int2 ed = __ldg(&g_edge[e + half]);
        uint2 h = __ldg(Hrows + (size_t)ed.x * 16 + sub);
        float v = __int_as_float(ed.y);
        float2 a01 = __half22float2(*(const __half2*)&h.x);
        float2 a23 = __half22float2(*(const __half2*)&h.y);
        acc.x += v * a01.x;
        acc.y += v * a01.y;
        acc.z += v * a23.x;
        acc.w += v * a23.y;
        e += 2;
    }
    if (e < end && half == 0) {
        int2 ed = __ldg(&g_edge[e]);
        uint2 h = __ldg(Hrows + (size_t)ed.x * 16 + sub);
        float v = __int_as_float(ed.y);
        float2 a01 = __half22float2(*(const __half2*)&h.x);
        float2 a23 = __half22float2(*(const __half2*)&h.y);
        acc.x += v * a01.x;
        acc.y += v * a01.y;
        acc.z += v * a23.x;
        acc.w += v * a23.y;
    }

    // merge parity halves
    acc.x += __shfl_down_sync(0xffffffffu, acc.x, 16);
    acc.y += __shfl_down_sync(0xffffffffu, acc.y, 16);
    acc.z += __shfl_down_sync(0xffffffffu, acc.z, 16);
    acc.w += __shfl_down_sync(0xffffffffu, acc.w, 16);

    float ss = acc.x * acc.x + acc.y * acc.y + acc.z * acc.z + acc.w * acc.w;
    #pragma unroll
    for (int o = 8; o; o >>= 1) ss += __shfl_xor_sync(0xffffffffu, ss, o);

    if (half == 0) {
        float nrm   = sqrtf(ss) + EPSV;
        float scale = tanhf(nrm) / nrm;
        uint2 hv;
        __half2 p01 = __floats2half2_rn(acc.x * scale, acc.y * scale);
        __half2 p23 = __floats2half2_rn(acc.z * scale, acc.w * scale);
        hv.x = *(const unsigned*)&p01;
        hv.y = *(const unsigned*)&p23;
        reinterpret_cast<uint2*>(Hout)[(size_t)warp * 16 + sub] = hv;
    }
}

// ---------------- final: Z = w0*X + sum_l w_l * H_l  (pure streaming) ----------------
__global__ __launch_bounds__(256)
void k_finalZ(const float* __restrict__ X, float* __restrict__ Z,
              const float* __restrict__ w, int n4) {
    int i = blockIdx.x * blockDim.x + threadIdx.x;
    if (i >= n4) return;
    float w0 = __ldg(w);
    float4 x = ((const float4*)X)[i];
    float4 z;
    z.x = w0 * x.x; z.y = w0 * x.y; z.z = w0 * x.z; z.w = w0 * x.w;
    #pragma unroll
    for (int l = 0; l < LMAX; l++) {
        float wl = __ldg(w + l + 1);
        uint2 hv = __ldg(reinterpret_cast<const uint2*>(g_Hl[l]) + i);
        float2 a01 = __half22float2(*(const __half2*)&hv.x);
        float2 a23 = __half22float2(*(const __half2*)&hv.y);
        z.x += wl * a01.x;
        z.y += wl * a01.y;
        z.z += wl * a23.x;
        z.w += wl * a23.y;
    }
    ((float4*)Z)[i] = z;
}

// ---------------- launch ----------------
extern "C" void kernel_launch(void* const* d_in, const int* in_sizes, int n_in,
                              void* d_out, int out_size) {
    const float* X    = (const float*)d_in[0];
    const float* vals = (const float*)d_in[1];
    const float* w    = (const float*)d_in[2];
    const int*   src  = (const int*)d_in[3];
    const int*   dst  = (const int*)d_in[4];
    float* Z = (float*)d_out;

    int n = in_sizes[0] / DIM;
    int e = in_sizes[1];
    int L = in_sizes[2] - 1;
    if (L > LMAX) L = LMAX;

    __half2* xh;
    cudaGetSymbolAddress((void**)&xh, g_Xh);
    __half2* hl[LMAX];
    {
        char* base;
        cudaGetSymbolAddress((void**)&base, g_Hl);
        size_t stride = (size_t)NMAX * (DIM / 2) * sizeof(__half2);
        for (int l = 0; l < LMAX; l++) hl[l] = (__half2*)(base + (size_t)l * stride);
    }

    int n4 = n * DIM / 4;
    int nb = (n + SCAN_B - 1) / SCAN_B;

    // ---- prep (zero deg/flags, X -> fp16) ----
    k_prep<<<(n4 + 255) / 256, 256>>>(X, xh, n, n4);
    // ---- CSR build ----
    k_hist<<<(e + 255) / 256, 256>>>(dst, e);
    k_scan<<<nb, SCAN_B>>>(n, nb);
    k_scatter<<<(e + 255) / 256, 256>>>(src, dst, vals, e);

    // ---- L propagation steps, storing every level ----
    int blocks = (n * 32 + 255) / 256;
    for (int l = 1; l <= L; l++) {
        const __half2* Hin = (l == 1) ? xh : hl[l - 2];
        k_spmm_renorm<<<blocks, 256>>>(Hin, hl[l - 1], n);
    }

    // ---- Z = w0*X + sum w_l H_l ----
    k_finalZ<<<(n4 + 255) / 256, 256>>>(X, Z, w, n4);
}